// round 13
// baseline (speedup 1.0000x reference)
#include <cuda_runtime.h>
#include <cuda_fp16.h>
#include <cstdint>

#define N_NODES 50000
#define N_EDGES 800000

// ===================== scratch =================================================
__device__ __half g_aggh[N_NODES * 512];
__device__ __half g_h1h[N_NODES * 512];
__device__ __half g_h2h[N_NODES * 512];
__device__ __half g_xh[N_NODES * 128];
__device__ __half g_wh[917504];
__device__ __half g_Pl[N_NODES * 256];
__device__ float  g_Pr[N_NODES * 256];
__device__ int    g_deg[N_NODES];
__device__ int    g_off[N_NODES + 1];
__device__ int    g_cur[N_NODES];
__device__ int    g_srcs[N_EDGES];
__device__ int    g_bsum[64];
__device__ int    g_boff[64];
__device__ int    g_idx64;

__device__ __forceinline__ void mma_f16(float* c, const uint32_t* a, const uint32_t* b) {
    asm volatile(
        "mma.sync.aligned.m16n8k16.row.col.f32.f16.f16.f32 "
        "{%0,%1,%2,%3}, {%4,%5,%6,%7}, {%8,%9}, {%0,%1,%2,%3};"
        : "+f"(c[0]), "+f"(c[1]), "+f"(c[2]), "+f"(c[3])
        : "r"(a[0]), "r"(a[1]), "r"(a[2]), "r"(a[3]), "r"(b[0]), "r"(b[1]));
}

__device__ __forceinline__ void ldsm_x4(uint32_t* r, uint32_t addr) {
    asm volatile("ldmatrix.sync.aligned.m8n8.x4.shared.b16 {%0,%1,%2,%3}, [%4];"
                 : "=r"(r[0]), "=r"(r[1]), "=r"(r[2]), "=r"(r[3]) : "r"(addr));
}
__device__ __forceinline__ void ldsm_x2(uint32_t* r, uint32_t addr) {
    asm volatile("ldmatrix.sync.aligned.m8n8.x2.shared.b16 {%0,%1}, [%2];"
                 : "=r"(r[0]), "=r"(r[1]) : "r"(addr));
}

__device__ __forceinline__ void cp_async16(uint32_t dst, const void* src, int sz) {
    asm volatile("cp.async.cg.shared.global [%0], [%1], 16, %2;"
                 :: "r"(dst), "l"(src), "r"(sz) : "memory");
}
#define CP_COMMIT() asm volatile("cp.async.commit_group;" ::: "memory")
#define CP_WAIT1()  asm volatile("cp.async.wait_group 1;" ::: "memory")

__device__ __forceinline__ uint32_t smem_u32(const void* p) {
    uint32_t a;
    asm("{ .reg .u64 t; cvta.to.shared.u64 t, %1; cvt.u32.u64 %0, t; }" : "=r"(a) : "l"(p));
    return a;
}

__device__ __forceinline__ void acc_u32h2(float2& a, uint32_t u) {
    __half2 h = *reinterpret_cast<__half2*>(&u);
    float2 f = __half22float2(h);
    a.x += f.x; a.y += f.y;
}
__device__ __forceinline__ uint32_t pack_h2(float x, float y) {
    __half2 h = __floats2half2_rn(x, y);
    return *reinterpret_cast<uint32_t*>(&h);
}

// ===================== fp32 -> fp16 conversion (x + weights) =================
struct RoundArgs { const float* s[7]; __half* d[7]; int n[7]; };
__global__ void round_all_kernel(RoundArgs ra) {
    int t = blockIdx.y;
    int n4 = ra.n[t] >> 2;
    const float4* s = (const float4*)ra.s[t];
    uint2* d = (uint2*)ra.d[t];
    for (int i = blockIdx.x * blockDim.x + threadIdx.x; i < n4; i += gridDim.x * blockDim.x) {
        float4 v = s[i];
        d[i] = make_uint2(pack_h2(v.x, v.y), pack_h2(v.z, v.w));
    }
}

// ===================== CSR build ==============================================
__global__ void zero_detect_kernel(const int* __restrict__ ei32) {
    int i = blockIdx.x * blockDim.x + threadIdx.x;
    if (i < N_NODES) { g_deg[i] = 0; g_cur[i] = 0; }
    if (blockIdx.x == 0 && threadIdx.x < 32) {
        int lane = threadIdx.x;
        int nz = 0;
#pragma unroll
        for (int t = 0; t < 32; t++) nz |= ei32[1 + 2 * (lane + 32 * t)];
        unsigned any = __ballot_sync(0xffffffffu, nz != 0);
        if (lane == 0) g_idx64 = (any == 0u);
    }
}

__device__ __forceinline__ int load_idx(const void* ei, long long pos) {
    if (g_idx64) return (int)((const long long*)ei)[pos];
    return ((const int*)ei)[pos];
}

// 2 edges per thread for ILP (latency-bound kernels)
__global__ void hist_kernel(const void* __restrict__ ei) {
    int e = (blockIdx.x * blockDim.x + threadIdx.x) * 2;
    if (e < N_EDGES) {
        int d0 = load_idx(ei, (long long)N_EDGES + e);
        int d1 = (e + 1 < N_EDGES) ? load_idx(ei, (long long)N_EDGES + e + 1) : -1;
        if ((unsigned)d0 < (unsigned)N_NODES) atomicAdd(&g_deg[d0], 1);
        if ((unsigned)d1 < (unsigned)N_NODES) atomicAdd(&g_deg[d1], 1);
    }
}

__global__ void scan1_kernel() {
    __shared__ int wsum[32];
    int tid = threadIdx.x, b = blockIdx.x;
    int idx = b * 1000 + tid;
    int v = (tid < 1000) ? g_deg[idx] : 0;
    int lane = tid & 31, w = tid >> 5;
    int ix = v;
#pragma unroll
    for (int o = 1; o < 32; o <<= 1) {
        int t = __shfl_up_sync(0xffffffffu, ix, o);
        if (lane >= o) ix += t;
    }
    if (lane == 31) wsum[w] = ix;
    __syncthreads();
    if (w == 0) {
        int t = wsum[lane];
#pragma unroll
        for (int o = 1; o < 32; o <<= 1) {
            int u = __shfl_up_sync(0xffffffffu, t, o);
            if (lane >= o) t += u;
        }
        wsum[lane] = t;
    }
    __syncthreads();
    int excl = ((w > 0) ? wsum[w - 1] : 0) + ix - v;
    if (tid < 1000) g_off[idx] = excl;
    if (tid == 1023) g_bsum[b] = wsum[31];
}

__global__ void scan2_kernel() {
    __shared__ int s[64];
    int tid = threadIdx.x;
    int v = (tid < 50) ? g_bsum[tid] : 0;
    s[tid] = v;
    __syncthreads();
#pragma unroll
    for (int o = 1; o < 64; o <<= 1) {
        int t = (tid >= o) ? s[tid - o] : 0;
        __syncthreads();
        s[tid] += t;
        __syncthreads();
    }
    if (tid < 50) g_boff[tid] = s[tid] - v;
    if (tid == 63) g_off[N_NODES] = s[63];
}

__global__ void scan3_kernel() {
    int tid = threadIdx.x, b = blockIdx.x;
    if (tid < 1000) g_off[b * 1000 + tid] += g_boff[b];
}

__global__ void scatter_kernel(const void* __restrict__ ei) {
    int e = (blockIdx.x * blockDim.x + threadIdx.x) * 2;
#pragma unroll
    for (int k = 0; k < 2; k++) {
        int ee = e + k;
        if (ee < N_EDGES) {
            int s = load_idx(ei, ee);
            int d = load_idx(ei, (long long)N_EDGES + ee);
            if ((unsigned)d < (unsigned)N_NODES && (unsigned)s < (unsigned)N_NODES) {
                int pos = atomicAdd(&g_cur[d], 1);
                g_srcs[g_off[d] + pos] = s;
            }
        }
    }
}

// ===================== fp16 mean aggregation (warp/node, unroll-4) ============
template <int D>
__global__ void aggregate_kernel(const __half* __restrict__ feat,
                                 __half* __restrict__ out) {
    int warp = (blockIdx.x * blockDim.x + threadIdx.x) >> 5;
    if (warp >= N_NODES) return;
    int lane = threadIdx.x & 31;
    int beg = g_off[warp];
    int end = g_off[warp + 1];

    if (D == 512) {
        float2 acc[8];
#pragma unroll
        for (int j = 0; j < 8; j++) acc[j] = make_float2(0.f, 0.f);
        int i = beg;
        for (; i + 3 < end; i += 4) {
            const uint4* p0 = (const uint4*)(feat + (size_t)g_srcs[i] * 512);
            const uint4* p1 = (const uint4*)(feat + (size_t)g_srcs[i + 1] * 512);
            const uint4* p2 = (const uint4*)(feat + (size_t)g_srcs[i + 2] * 512);
            const uint4* p3 = (const uint4*)(feat + (size_t)g_srcs[i + 3] * 512);
#pragma unroll
            for (int c = 0; c < 2; c++) {
                uint4 v0 = __ldg(&p0[lane + 32 * c]);
                uint4 v1 = __ldg(&p1[lane + 32 * c]);
                uint4 v2 = __ldg(&p2[lane + 32 * c]);
                uint4 v3 = __ldg(&p3[lane + 32 * c]);
                acc_u32h2(acc[4 * c + 0], v0.x); acc_u32h2(acc[4 * c + 0], v1.x);
                acc_u32h2(acc[4 * c + 0], v2.x); acc_u32h2(acc[4 * c + 0], v3.x);
                acc_u32h2(acc[4 * c + 1], v0.y); acc_u32h2(acc[4 * c + 1], v1.y);
                acc_u32h2(acc[4 * c + 1], v2.y); acc_u32h2(acc[4 * c + 1], v3.y);
                acc_u32h2(acc[4 * c + 2], v0.z); acc_u32h2(acc[4 * c + 2], v1.z);
                acc_u32h2(acc[4 * c + 2], v2.z); acc_u32h2(acc[4 * c + 2], v3.z);
                acc_u32h2(acc[4 * c + 3], v0.w); acc_u32h2(acc[4 * c + 3], v1.w);
                acc_u32h2(acc[4 * c + 3], v2.w); acc_u32h2(acc[4 * c + 3], v3.w);
            }
        }
        for (; i < end; i++) {
            const uint4* p0 = (const uint4*)(feat + (size_t)g_srcs[i] * 512);
#pragma unroll
            for (int c = 0; c < 2; c++) {
                uint4 v0 = __ldg(&p0[lane + 32 * c]);
                acc_u32h2(acc[4 * c + 0], v0.x);
                acc_u32h2(acc[4 * c + 1], v0.y);
                acc_u32h2(acc[4 * c + 2], v0.z);
                acc_u32h2(acc[4 * c + 3], v0.w);
            }
        }
        int cnt = end - beg;
        float inv = 1.0f / (float)(cnt > 0 ? cnt : 1);
        uint4* o = (uint4*)(out + (size_t)warp * 512);
#pragma unroll
        for (int c = 0; c < 2; c++) {
            uint4 v;
            v.x = pack_h2(acc[4 * c + 0].x * inv, acc[4 * c + 0].y * inv);
            v.y = pack_h2(acc[4 * c + 1].x * inv, acc[4 * c + 1].y * inv);
            v.z = pack_h2(acc[4 * c + 2].x * inv, acc[4 * c + 2].y * inv);
            v.w = pack_h2(acc[4 * c + 3].x * inv, acc[4 * c + 3].y * inv);
            o[lane + 32 * c] = v;
        }
    } else {  // D == 128
        float2 acc[2];
        acc[0] = make_float2(0.f, 0.f); acc[1] = make_float2(0.f, 0.f);
        int i = beg;
        for (; i + 3 < end; i += 4) {
            uint2 v0 = __ldg((const uint2*)(feat + (size_t)g_srcs[i] * 128) + lane);
            uint2 v1 = __ldg((const uint2*)(feat + (size_t)g_srcs[i + 1] * 128) + lane);
            uint2 v2 = __ldg((const uint2*)(feat + (size_t)g_srcs[i + 2] * 128) + lane);
            uint2 v3 = __ldg((const uint2*)(feat + (size_t)g_srcs[i + 3] * 128) + lane);
            acc_u32h2(acc[0], v0.x); acc_u32h2(acc[0], v1.x);
            acc_u32h2(acc[0], v2.x); acc_u32h2(acc[0], v3.x);
            acc_u32h2(acc[1], v0.y); acc_u32h2(acc[1], v1.y);
            acc_u32h2(acc[1], v2.y); acc_u32h2(acc[1], v3.y);
        }
        for (; i < end; i++) {
            uint2 v0 = __ldg((const uint2*)(feat + (size_t)g_srcs[i] * 128) + lane);
            acc_u32h2(acc[0], v0.x);
            acc_u32h2(acc[1], v0.y);
        }
        int cnt = end - beg;
        float inv = 1.0f / (float)(cnt > 0 ? cnt : 1);
        uint2 v;
        v.x = pack_h2(acc[0].x * inv, acc[0].y * inv);
        v.y = pack_h2(acc[1].x * inv, acc[1].y * inv);
        *((uint2*)(out + (size_t)warp * 128) + lane) = v;
    }
}

// ===================== layer-2 final: out = mean(Pl[src]) + Pr[row] + b ========
__global__ void final_agg_kernel(const __half* __restrict__ Pl,
                                 const float* __restrict__ Pr,
                                 const float* __restrict__ bias,
                                 float* __restrict__ out) {
    int warp = (blockIdx.x * blockDim.x + threadIdx.x) >> 5;
    if (warp >= N_NODES) return;
    int lane = threadIdx.x & 31;
    int beg = g_off[warp];
    int end = g_off[warp + 1];

    float2 acc[4];
#pragma unroll
    for (int j = 0; j < 4; j++) acc[j] = make_float2(0.f, 0.f);

    int i = beg;
    for (; i + 3 < end; i += 4) {
        uint4 v0 = __ldg((const uint4*)(Pl + (size_t)g_srcs[i] * 256) + lane);
        uint4 v1 = __ldg((const uint4*)(Pl + (size_t)g_srcs[i + 1] * 256) + lane);
        uint4 v2 = __ldg((const uint4*)(Pl + (size_t)g_srcs[i + 2] * 256) + lane);
        uint4 v3 = __ldg((const uint4*)(Pl + (size_t)g_srcs[i + 3] * 256) + lane);
        acc_u32h2(acc[0], v0.x); acc_u32h2(acc[0], v1.x);
        acc_u32h2(acc[0], v2.x); acc_u32h2(acc[0], v3.x);
        acc_u32h2(acc[1], v0.y); acc_u32h2(acc[1], v1.y);
        acc_u32h2(acc[1], v2.y); acc_u32h2(acc[1], v3.y);
        acc_u32h2(acc[2], v0.z); acc_u32h2(acc[2], v1.z);
        acc_u32h2(acc[2], v2.z); acc_u32h2(acc[2], v3.z);
        acc_u32h2(acc[3], v0.w); acc_u32h2(acc[3], v1.w);
        acc_u32h2(acc[3], v2.w); acc_u32h2(acc[3], v3.w);
    }
    for (; i < end; i++) {
        uint4 v0 = __ldg((const uint4*)(Pl + (size_t)g_srcs[i] * 256) + lane);
        acc_u32h2(acc[0], v0.x);
        acc_u32h2(acc[1], v0.y);
        acc_u32h2(acc[2], v0.z);
        acc_u32h2(acc[3], v0.w);
    }
    int cnt = end - beg;
    float inv = 1.0f / (float)(cnt > 0 ? cnt : 1);
    const float4* pr = (const float4*)(Pr + (size_t)warp * 256 + lane * 8);
    const float4* bb = (const float4*)(bias + lane * 8);
    float4* o = (float4*)(out + (size_t)warp * 256 + lane * 8);
    float4 r0 = __ldg(&pr[0]), r1 = __ldg(&pr[1]);
    float4 b0 = bb[0], b1 = bb[1];
    float4 v0, v1;
    v0.x = acc[0].x * inv + r0.x + b0.x;
    v0.y = acc[0].y * inv + r0.y + b0.y;
    v0.z = acc[1].x * inv + r0.z + b0.z;
    v0.w = acc[1].y * inv + r0.w + b0.w;
    v1.x = acc[2].x * inv + r1.x + b1.x;
    v1.y = acc[2].y * inv + r1.y + b1.y;
    v1.z = acc[3].x * inv + r1.z + b1.z;
    v1.w = acc[3].y * inv + r1.w + b1.w;
    o[0] = v0; o[1] = v1;
}

// ===================== fp16 mma GEMM, cp.async 3-stage, ldmatrix ==============
// DUAL:   C = A1@W1^T + A2@W2^T (+bias,+relu), fp16 out.
// SPLIT:  C = A1@W1^T; cols < Nsplit -> fp16 Cout (stride Nsplit),
//                       cols >= Nsplit -> fp32 Cout2 (stride N-Nsplit).
#define GEMM_SMEM 98304

template <bool DUAL, bool RELU, bool SPLIT>
__global__ void __launch_bounds__(256, 2)
gemm_h_kernel(const __half* __restrict__ A1, const __half* __restrict__ W1,
              const __half* __restrict__ A2, const __half* __restrict__ W2,
              const float* __restrict__ bias, void* __restrict__ Cout,
              float* __restrict__ Cout2, int M, int N, int K, int Nsplit) {
    extern __shared__ uint32_t sm[];
    uint32_t smb = smem_u32(sm);

    int tid = threadIdx.x, lane = tid & 31, wid = tid >> 5;
    int bm = blockIdx.x * 128, bn = blockIdx.y * 128;
    int wm = wid & 1, wn = wid >> 1;

    float acc[4][4][4];
#pragma unroll
    for (int mi = 0; mi < 4; mi++)
#pragma unroll
        for (int ni = 0; ni < 4; ni++)
#pragma unroll
            for (int r = 0; r < 4; r++) acc[mi][ni][r] = 0.0f;

    int chunks = K >> 6;                 // BK = 64 halves
    int total = DUAL ? 2 * chunks : chunks;

    auto prefetch = [&](int it, int stage) {
        int pass = DUAL ? (it >= chunks) : 0;
        int k0 = ((DUAL && pass) ? it - chunks : it) << 6;
        const __half* A = (DUAL && pass) ? A2 : A1;
        const __half* W = (DUAL && pass) ? W2 : W1;
        uint32_t abase = smb + stage * 32768;
        uint32_t bbase = abase + 16384;
#pragma unroll
        for (int t = 0; t < 4; t++) {
            int idx = tid + t * 256;
            int row = idx >> 3, q = idx & 7;
            uint32_t swz = (uint32_t)(q ^ (row & 7)) << 4;
            int gr = bm + row;
            const __half* srcA = A + (size_t)(gr < M ? gr : 0) * K + k0 + q * 8;
            cp_async16(abase + row * 128 + swz, srcA, (gr < M) ? 16 : 0);
            const __half* srcB = W + (size_t)(bn + row) * K + k0 + q * 8;
            cp_async16(bbase + row * 128 + swz, srcB, 16);
        }
    };

    prefetch(0, 0); CP_COMMIT();
    prefetch(1, 1); CP_COMMIT();

    uint32_t a_row_off = (uint32_t)(wm * 64 + (lane & 15)) * 128;
    uint32_t a_gx = (uint32_t)((lane & 7) ^ ((lane >> 4) & 1));
    uint32_t b_row_off = (uint32_t)(wn * 32 + (lane & 7)) * 128;
    uint32_t b_gx = (uint32_t)((lane & 7) ^ ((lane >> 3) & 1));

    int stage = 0;
    for (int it = 0; it < total; it++) {
        CP_WAIT1();
        __syncthreads();
        if (it + 2 < total) {
            int ps = stage + 2; if (ps >= 3) ps -= 3;
            prefetch(it + 2, ps);
        }
        CP_COMMIT();

        uint32_t abase = smb + (uint32_t)stage * 32768;
        uint32_t bbase = abase + 16384;
#pragma unroll
        for (int ks = 0; ks < 4; ks++) {
            uint32_t ag = ((2u * ks) ^ a_gx) << 4;
            uint32_t bg = ((2u * ks) ^ b_gx) << 4;
            uint32_t a[4][4], b[4][2];
#pragma unroll
            for (int mi = 0; mi < 4; mi++)
                ldsm_x4(a[mi], abase + a_row_off + mi * 2048 + ag);
#pragma unroll
            for (int ni = 0; ni < 4; ni++)
                ldsm_x2(b[ni], bbase + b_row_off + ni * 1024 + bg);
#pragma unroll
            for (int mi = 0; mi < 4; mi++)
#pragma unroll
                for (int ni = 0; ni < 4; ni++)
                    mma_f16(acc[mi][ni], a[mi], b[ni]);
        }
        if (++stage == 3) stage = 0;
    }

    int qr = lane >> 2, qc2 = (lane & 3) * 2;
#pragma unroll
    for (int mi = 0; mi < 4; mi++) {
#pragma unroll
        for (int half = 0; half < 2; half++) {
            int row = bm + wm * 64 + mi * 16 + qr + half * 8;
            if (row >= M) continue;
#pragma unroll
            for (int ni = 0; ni < 4; ni++) {
                int col = bn + wn * 32 + ni * 8 + qc2;
                float ox = acc[mi][ni][half * 2 + 0];
                float oy = acc[mi][ni][half * 2 + 1];
                if (SPLIT) {
                    if (col < Nsplit) {
                        *(uint32_t*)((__half*)Cout + (size_t)row * Nsplit + col) = pack_h2(ox, oy);
                    } else {
                        *(float2*)(Cout2 + (size_t)row * (N - Nsplit) + (col - Nsplit)) =
                            make_float2(ox, oy);
                    }
                } else {
                    ox += bias[col]; oy += bias[col + 1];
                    if (RELU) { ox = fmaxf(ox, 0.f); oy = fmaxf(oy, 0.f); }
                    *(uint32_t*)((__half*)Cout + (size_t)row * N + col) = pack_h2(ox, oy);
                }
            }
        }
    }
}

// ===================== launch ==================================================
extern "C" void kernel_launch(void* const* d_in, const int* in_sizes, int n_in,
                              void* d_out, int out_size) {
    const float* x   = (const float*)d_in[0];
    const void*  ei  = d_in[1];
    const float* Wl0 = (const float*)d_in[2];
    const float* bl0 = (const float*)d_in[3];
    const float* Wr0 = (const float*)d_in[4];
    const float* Wl1 = (const float*)d_in[5];
    const float* bl1 = (const float*)d_in[6];
    const float* Wr1 = (const float*)d_in[7];
    const float* Wl2 = (const float*)d_in[8];
    const float* bl2 = (const float*)d_in[9];
    const float* Wr2 = (const float*)d_in[10];
    float*       out = (float*)d_out;

    int M = in_sizes[0] / 128;   // 50000

    __half *aggh, *h1h, *h2h, *xh, *wh, *Pl;
    float* Pr;
    cudaGetSymbolAddress((void**)&aggh, g_aggh);
    cudaGetSymbolAddress((void**)&h1h,  g_h1h);
    cudaGetSymbolAddress((void**)&h2h,  g_h2h);
    cudaGetSymbolAddress((void**)&xh,   g_xh);
    cudaGetSymbolAddress((void**)&wh,   g_wh);
    cudaGetSymbolAddress((void**)&Pl,   g_Pl);
    cudaGetSymbolAddress((void**)&Pr,   g_Pr);

    __half* wl0h = wh;
    __half* wr0h = wh + 65536;
    __half* wl1h = wh + 131072;
    __half* wr1h = wh + 393216;
    __half* wl2h = wh + 655360;   // [Wl2;Wr2] contiguous
    __half* wr2h = wh + 786432;

    cudaFuncSetAttribute(gemm_h_kernel<true, true, false>,
                         cudaFuncAttributeMaxDynamicSharedMemorySize, GEMM_SMEM);
    cudaFuncSetAttribute(gemm_h_kernel<false, false, true>,
                         cudaFuncAttributeMaxDynamicSharedMemorySize, GEMM_SMEM);

    static cudaStream_t s2 = nullptr;
    static cudaEvent_t eFork = nullptr, eJoin = nullptr;
    if (!s2) {
        cudaStreamCreateWithFlags(&s2, cudaStreamNonBlocking);
        cudaEventCreateWithFlags(&eFork, cudaEventDisableTiming);
        cudaEventCreateWithFlags(&eJoin, cudaEventDisableTiming);
    }

    // ---- fork: fp16 conversion on s2, CSR build on the main stream ----
    cudaEventRecord(eFork, 0);
    cudaStreamWaitEvent(s2, eFork, 0);

    RoundArgs ra;
    ra.s[0] = x;   ra.d[0] = xh;   ra.n[0] = M * 128;
    ra.s[1] = Wl0; ra.d[1] = wl0h; ra.n[1] = 512 * 128;
    ra.s[2] = Wr0; ra.d[2] = wr0h; ra.n[2] = 512 * 128;
    ra.s[3] = Wl1; ra.d[3] = wl1h; ra.n[3] = 512 * 512;
    ra.s[4] = Wr1; ra.d[4] = wr1h; ra.n[4] = 512 * 512;
    ra.s[5] = Wl2; ra.d[5] = wl2h; ra.n[5] = 256 * 512;
    ra.s[6] = Wr2; ra.d[6] = wr2h; ra.n[6] = 256 * 512;
    round_all_kernel<<<dim3(256, 7), 256, 0, s2>>>(ra);
    cudaEventRecord(eJoin, s2);

    // CSR build (main stream)
    zero_detect_kernel<<<(N_NODES + 255) / 256, 256>>>((const int*)ei);
    hist_kernel<<<(N_EDGES / 2 + 255) / 256, 256>>>(ei);
    scan1_kernel<<<50, 1024>>>();
    scan2_kernel<<<1, 64>>>();
    scan3_kernel<<<50, 1024>>>();
    scatter_kernel<<<(N_EDGES / 2 + 255) / 256, 256>>>(ei);

    // ---- join ----
    cudaStreamWaitEvent(0, eJoin, 0);

    int aggBlocks = (N_NODES * 32 + 255) / 256;
    int mTiles = (M + 127) / 128;

    // Layer 0: 128 -> 512, relu (dual GEMM)
    aggregate_kernel<128><<<aggBlocks, 256>>>(xh, aggh);
    gemm_h_kernel<true, true, false><<<dim3(mTiles, 4), 256, GEMM_SMEM>>>(
        aggh, wl0h, xh, wr0h, bl0, h1h, nullptr, M, 512, 128, 0);

    // Layer 1: 512 -> 512, relu (dual GEMM)
    aggregate_kernel<512><<<aggBlocks, 256>>>(h1h, aggh);
    gemm_h_kernel<true, true, false><<<dim3(mTiles, 4), 256, GEMM_SMEM>>>(
        aggh, wl1h, h1h, wr1h, bl1, h2h, nullptr, M, 512, 512, 0);

    // Layer 2 (projection-first, single split GEMM over [Wl2;Wr2])
    gemm_h_kernel<false, false, true><<<dim3(mTiles, 4), 256, GEMM_SMEM>>>(
        h2h, wl2h, nullptr, nullptr, nullptr, Pl, Pr, M, 512, 512, 256);
    final_agg_kernel<<<aggBlocks, 256>>>(Pl, Pr, bl2, out);
}

// round 14
// speedup vs baseline: 1.4810x; 1.4810x over previous
#include <cuda_runtime.h>
#include <cuda_fp16.h>
#include <cstdint>

#define N_NODES 50000
#define N_EDGES 800000

// ===================== scratch =================================================
__device__ __half g_aggh[N_NODES * 512];
__device__ __half g_h1h[N_NODES * 512];
__device__ __half g_h2h[N_NODES * 512];
__device__ __half g_xh[N_NODES * 128];
__device__ __half g_wh[917504];
__device__ __half g_Pl[N_NODES * 256];
__device__ float  g_Pr[N_NODES * 256];
__device__ int    g_deg[N_NODES];
__device__ int    g_off[N_NODES + 1];
__device__ int    g_cur[N_NODES];
__device__ int    g_srcs[N_EDGES];
__device__ int    g_bsum[64];
__device__ int    g_boff[64];
__device__ int    g_idx64;

__device__ __forceinline__ void mma_f16(float* c, const uint32_t* a, const uint32_t* b) {
    asm volatile(
        "mma.sync.aligned.m16n8k16.row.col.f32.f16.f16.f32 "
        "{%0,%1,%2,%3}, {%4,%5,%6,%7}, {%8,%9}, {%0,%1,%2,%3};"
        : "+f"(c[0]), "+f"(c[1]), "+f"(c[2]), "+f"(c[3])
        : "r"(a[0]), "r"(a[1]), "r"(a[2]), "r"(a[3]), "r"(b[0]), "r"(b[1]));
}

__device__ __forceinline__ void ldsm_x4(uint32_t* r, uint32_t addr) {
    asm volatile("ldmatrix.sync.aligned.m8n8.x4.shared.b16 {%0,%1,%2,%3}, [%4];"
                 : "=r"(r[0]), "=r"(r[1]), "=r"(r[2]), "=r"(r[3]) : "r"(addr));
}
__device__ __forceinline__ void ldsm_x2(uint32_t* r, uint32_t addr) {
    asm volatile("ldmatrix.sync.aligned.m8n8.x2.shared.b16 {%0,%1}, [%2];"
                 : "=r"(r[0]), "=r"(r[1]) : "r"(addr));
}

__device__ __forceinline__ void cp_async16(uint32_t dst, const void* src, int sz) {
    asm volatile("cp.async.cg.shared.global [%0], [%1], 16, %2;"
                 :: "r"(dst), "l"(src), "r"(sz) : "memory");
}
#define CP_COMMIT() asm volatile("cp.async.commit_group;" ::: "memory")
#define CP_WAIT1()  asm volatile("cp.async.wait_group 1;" ::: "memory")

__device__ __forceinline__ uint32_t smem_u32(const void* p) {
    uint32_t a;
    asm("{ .reg .u64 t; cvta.to.shared.u64 t, %1; cvt.u32.u64 %0, t; }" : "=r"(a) : "l"(p));
    return a;
}

__device__ __forceinline__ void acc_u32h2(float2& a, uint32_t u) {
    __half2 h = *reinterpret_cast<__half2*>(&u);
    float2 f = __half22float2(h);
    a.x += f.x; a.y += f.y;
}
__device__ __forceinline__ uint32_t pack_h2(float x, float y) {
    __half2 h = __floats2half2_rn(x, y);
    return *reinterpret_cast<uint32_t*>(&h);
}

// ===================== fp32 -> fp16 conversion (x + weights) =================
struct RoundArgs { const float* s[7]; __half* d[7]; int n[7]; };
__global__ void round_all_kernel(RoundArgs ra) {
    int t = blockIdx.y;
    int n4 = ra.n[t] >> 2;
    const float4* s = (const float4*)ra.s[t];
    uint2* d = (uint2*)ra.d[t];
    for (int i = blockIdx.x * blockDim.x + threadIdx.x; i < n4; i += gridDim.x * blockDim.x) {
        float4 v = s[i];
        d[i] = make_uint2(pack_h2(v.x, v.y), pack_h2(v.z, v.w));
    }
}

// ===================== CSR build ==============================================
__global__ void zero_detect_kernel(const int* __restrict__ ei32) {
    int i = blockIdx.x * blockDim.x + threadIdx.x;
    if (i < N_NODES) { g_deg[i] = 0; g_cur[i] = 0; }
    if (blockIdx.x == 0 && threadIdx.x < 32) {
        int lane = threadIdx.x;
        int nz = 0;
#pragma unroll
        for (int t = 0; t < 32; t++) nz |= ei32[1 + 2 * (lane + 32 * t)];
        unsigned any = __ballot_sync(0xffffffffu, nz != 0);
        if (lane == 0) g_idx64 = (any == 0u);
    }
}

__device__ __forceinline__ int load_idx(const void* ei, long long pos) {
    if (g_idx64) return (int)((const long long*)ei)[pos];
    return ((const int*)ei)[pos];
}

__global__ void hist_kernel(const void* __restrict__ ei) {
    int e = blockIdx.x * blockDim.x + threadIdx.x;
    if (e < N_EDGES) {
        int d = load_idx(ei, (long long)N_EDGES + e);
        if ((unsigned)d < (unsigned)N_NODES) atomicAdd(&g_deg[d], 1);
    }
}

__global__ void scan1_kernel() {
    __shared__ int wsum[32];
    int tid = threadIdx.x, b = blockIdx.x;
    int idx = b * 1000 + tid;
    int v = (tid < 1000) ? g_deg[idx] : 0;
    int lane = tid & 31, w = tid >> 5;
    int ix = v;
#pragma unroll
    for (int o = 1; o < 32; o <<= 1) {
        int t = __shfl_up_sync(0xffffffffu, ix, o);
        if (lane >= o) ix += t;
    }
    if (lane == 31) wsum[w] = ix;
    __syncthreads();
    if (w == 0) {
        int t = wsum[lane];
#pragma unroll
        for (int o = 1; o < 32; o <<= 1) {
            int u = __shfl_up_sync(0xffffffffu, t, o);
            if (lane >= o) t += u;
        }
        wsum[lane] = t;
    }
    __syncthreads();
    int excl = ((w > 0) ? wsum[w - 1] : 0) + ix - v;
    if (tid < 1000) g_off[idx] = excl;
    if (tid == 1023) g_bsum[b] = wsum[31];
}

__global__ void scan2_kernel() {
    __shared__ int s[64];
    int tid = threadIdx.x;
    int v = (tid < 50) ? g_bsum[tid] : 0;
    s[tid] = v;
    __syncthreads();
#pragma unroll
    for (int o = 1; o < 64; o <<= 1) {
        int t = (tid >= o) ? s[tid - o] : 0;
        __syncthreads();
        s[tid] += t;
        __syncthreads();
    }
    if (tid < 50) g_boff[tid] = s[tid] - v;
    if (tid == 63) g_off[N_NODES] = s[63];
}

__global__ void scan3_kernel() {
    int tid = threadIdx.x, b = blockIdx.x;
    if (tid < 1000) g_off[b * 1000 + tid] += g_boff[b];
}

__global__ void scatter_kernel(const void* __restrict__ ei) {
    int e = blockIdx.x * blockDim.x + threadIdx.x;
    if (e < N_EDGES) {
        int s = load_idx(ei, e);
        int d = load_idx(ei, (long long)N_EDGES + e);
        if ((unsigned)d < (unsigned)N_NODES && (unsigned)s < (unsigned)N_NODES) {
            int pos = atomicAdd(&g_cur[d], 1);
            g_srcs[g_off[d] + pos] = s;
        }
    }
}

// ===================== fp16 mean aggregation (warp/node, unroll-4) ============
template <int D>
__global__ void aggregate_kernel(const __half* __restrict__ feat,
                                 __half* __restrict__ out) {
    int warp = (blockIdx.x * blockDim.x + threadIdx.x) >> 5;
    if (warp >= N_NODES) return;
    int lane = threadIdx.x & 31;
    int beg = g_off[warp];
    int end = g_off[warp + 1];

    if (D == 512) {
        float2 acc[8];
#pragma unroll
        for (int j = 0; j < 8; j++) acc[j] = make_float2(0.f, 0.f);
        int i = beg;
        for (; i + 3 < end; i += 4) {
            const uint4* p0 = (const uint4*)(feat + (size_t)g_srcs[i] * 512);
            const uint4* p1 = (const uint4*)(feat + (size_t)g_srcs[i + 1] * 512);
            const uint4* p2 = (const uint4*)(feat + (size_t)g_srcs[i + 2] * 512);
            const uint4* p3 = (const uint4*)(feat + (size_t)g_srcs[i + 3] * 512);
#pragma unroll
            for (int c = 0; c < 2; c++) {
                uint4 v0 = __ldg(&p0[lane + 32 * c]);
                uint4 v1 = __ldg(&p1[lane + 32 * c]);
                uint4 v2 = __ldg(&p2[lane + 32 * c]);
                uint4 v3 = __ldg(&p3[lane + 32 * c]);
                acc_u32h2(acc[4 * c + 0], v0.x); acc_u32h2(acc[4 * c + 0], v1.x);
                acc_u32h2(acc[4 * c + 0], v2.x); acc_u32h2(acc[4 * c + 0], v3.x);
                acc_u32h2(acc[4 * c + 1], v0.y); acc_u32h2(acc[4 * c + 1], v1.y);
                acc_u32h2(acc[4 * c + 1], v2.y); acc_u32h2(acc[4 * c + 1], v3.y);
                acc_u32h2(acc[4 * c + 2], v0.z); acc_u32h2(acc[4 * c + 2], v1.z);
                acc_u32h2(acc[4 * c + 2], v2.z); acc_u32h2(acc[4 * c + 2], v3.z);
                acc_u32h2(acc[4 * c + 3], v0.w); acc_u32h2(acc[4 * c + 3], v1.w);
                acc_u32h2(acc[4 * c + 3], v2.w); acc_u32h2(acc[4 * c + 3], v3.w);
            }
        }
        for (; i < end; i++) {
            const uint4* p0 = (const uint4*)(feat + (size_t)g_srcs[i] * 512);
#pragma unroll
            for (int c = 0; c < 2; c++) {
                uint4 v0 = __ldg(&p0[lane + 32 * c]);
                acc_u32h2(acc[4 * c + 0], v0.x);
                acc_u32h2(acc[4 * c + 1], v0.y);
                acc_u32h2(acc[4 * c + 2], v0.z);
                acc_u32h2(acc[4 * c + 3], v0.w);
            }
        }
        int cnt = end - beg;
        float inv = 1.0f / (float)(cnt > 0 ? cnt : 1);
        uint4* o = (uint4*)(out + (size_t)warp * 512);
#pragma unroll
        for (int c = 0; c < 2; c++) {
            uint4 v;
            v.x = pack_h2(acc[4 * c + 0].x * inv, acc[4 * c + 0].y * inv);
            v.y = pack_h2(acc[4 * c + 1].x * inv, acc[4 * c + 1].y * inv);
            v.z = pack_h2(acc[4 * c + 2].x * inv, acc[4 * c + 2].y * inv);
            v.w = pack_h2(acc[4 * c + 3].x * inv, acc[4 * c + 3].y * inv);
            o[lane + 32 * c] = v;
        }
    } else {  // D == 128
        float2 acc[2];
        acc[0] = make_float2(0.f, 0.f); acc[1] = make_float2(0.f, 0.f);
        int i = beg;
        for (; i + 3 < end; i += 4) {
            uint2 v0 = __ldg((const uint2*)(feat + (size_t)g_srcs[i] * 128) + lane);
            uint2 v1 = __ldg((const uint2*)(feat + (size_t)g_srcs[i + 1] * 128) + lane);
            uint2 v2 = __ldg((const uint2*)(feat + (size_t)g_srcs[i + 2] * 128) + lane);
            uint2 v3 = __ldg((const uint2*)(feat + (size_t)g_srcs[i + 3] * 128) + lane);
            acc_u32h2(acc[0], v0.x); acc_u32h2(acc[0], v1.x);
            acc_u32h2(acc[0], v2.x); acc_u32h2(acc[0], v3.x);
            acc_u32h2(acc[1], v0.y); acc_u32h2(acc[1], v1.y);
            acc_u32h2(acc[1], v2.y); acc_u32h2(acc[1], v3.y);
        }
        for (; i < end; i++) {
            uint2 v0 = __ldg((const uint2*)(feat + (size_t)g_srcs[i] * 128) + lane);
            acc_u32h2(acc[0], v0.x);
            acc_u32h2(acc[1], v0.y);
        }
        int cnt = end - beg;
        float inv = 1.0f / (float)(cnt > 0 ? cnt : 1);
        uint2 v;
        v.x = pack_h2(acc[0].x * inv, acc[0].y * inv);
        v.y = pack_h2(acc[1].x * inv, acc[1].y * inv);
        *((uint2*)(out + (size_t)warp * 128) + lane) = v;
    }
}

// ===================== layer-2 final: out = mean(Pl[src]) + Pr[row] + b ========
__global__ void final_agg_kernel(const __half* __restrict__ Pl,
                                 const float* __restrict__ Pr,
                                 const float* __restrict__ bias,
                                 float* __restrict__ out) {
    int warp = (blockIdx.x * blockDim.x + threadIdx.x) >> 5;
    if (warp >= N_NODES) return;
    int lane = threadIdx.x & 31;
    int beg = g_off[warp];
    int end = g_off[warp + 1];

    float2 acc[4];
#pragma unroll
    for (int j = 0; j < 4; j++) acc[j] = make_float2(0.f, 0.f);

    int i = beg;
    for (; i + 3 < end; i += 4) {
        uint4 v0 = __ldg((const uint4*)(Pl + (size_t)g_srcs[i] * 256) + lane);
        uint4 v1 = __ldg((const uint4*)(Pl + (size_t)g_srcs[i + 1] * 256) + lane);
        uint4 v2 = __ldg((const uint4*)(Pl + (size_t)g_srcs[i + 2] * 256) + lane);
        uint4 v3 = __ldg((const uint4*)(Pl + (size_t)g_srcs[i + 3] * 256) + lane);
        acc_u32h2(acc[0], v0.x); acc_u32h2(acc[0], v1.x);
        acc_u32h2(acc[0], v2.x); acc_u32h2(acc[0], v3.x);
        acc_u32h2(acc[1], v0.y); acc_u32h2(acc[1], v1.y);
        acc_u32h2(acc[1], v2.y); acc_u32h2(acc[1], v3.y);
        acc_u32h2(acc[2], v0.z); acc_u32h2(acc[2], v1.z);
        acc_u32h2(acc[2], v2.z); acc_u32h2(acc[2], v3.z);
        acc_u32h2(acc[3], v0.w); acc_u32h2(acc[3], v1.w);
        acc_u32h2(acc[3], v2.w); acc_u32h2(acc[3], v3.w);
    }
    for (; i < end; i++) {
        uint4 v0 = __ldg((const uint4*)(Pl + (size_t)g_srcs[i] * 256) + lane);
        acc_u32h2(acc[0], v0.x);
        acc_u32h2(acc[1], v0.y);
        acc_u32h2(acc[2], v0.z);
        acc_u32h2(acc[3], v0.w);
    }
    int cnt = end - beg;
    float inv = 1.0f / (float)(cnt > 0 ? cnt : 1);
    const float4* pr = (const float4*)(Pr + (size_t)warp * 256 + lane * 8);
    const float4* bb = (const float4*)(bias + lane * 8);
    float4* o = (float4*)(out + (size_t)warp * 256 + lane * 8);
    float4 r0 = __ldg(&pr[0]), r1 = __ldg(&pr[1]);
    float4 b0 = bb[0], b1 = bb[1];
    float4 v0, v1;
    v0.x = acc[0].x * inv + r0.x + b0.x;
    v0.y = acc[0].y * inv + r0.y + b0.y;
    v0.z = acc[1].x * inv + r0.z + b0.z;
    v0.w = acc[1].y * inv + r0.w + b0.w;
    v1.x = acc[2].x * inv + r1.x + b1.x;
    v1.y = acc[2].y * inv + r1.y + b1.y;
    v1.z = acc[3].x * inv + r1.z + b1.z;
    v1.w = acc[3].y * inv + r1.w + b1.w;
    o[0] = v0; o[1] = v1;
}

// ===================== fp16 mma GEMM, cp.async 3-stage, ldmatrix ==============
// DUAL:   C = A1@W1^T + A2@W2^T (+bias,+relu), fp16 out.
// SPLIT:  C = A1@W1^T; cols < Nsplit -> fp16 Cout (stride Nsplit),
//                       cols >= Nsplit -> fp32 Cout2 (stride N-Nsplit).
#define GEMM_SMEM 98304

template <bool DUAL, bool RELU, bool SPLIT>
__global__ void __launch_bounds__(256, 2)
gemm_h_kernel(const __half* __restrict__ A1, const __half* __restrict__ W1,
              const __half* __restrict__ A2, const __half* __restrict__ W2,
              const float* __restrict__ bias, void* __restrict__ Cout,
              float* __restrict__ Cout2, int M, int N, int K, int Nsplit) {
    extern __shared__ uint32_t sm[];
    uint32_t smb = smem_u32(sm);

    int tid = threadIdx.x, lane = tid & 31, wid = tid >> 5;
    int bm = blockIdx.x * 128, bn = blockIdx.y * 128;
    int wm = wid & 1, wn = wid >> 1;

    float acc[4][4][4];
#pragma unroll
    for (int mi = 0; mi < 4; mi++)
#pragma unroll
        for (int ni = 0; ni < 4; ni++)
#pragma unroll
            for (int r = 0; r < 4; r++) acc[mi][ni][r] = 0.0f;

    int chunks = K >> 6;                 // BK = 64 halves
    int total = DUAL ? 2 * chunks : chunks;

    auto prefetch = [&](int it, int stage) {
        int pass = DUAL ? (it >= chunks) : 0;
        int k0 = ((DUAL && pass) ? it - chunks : it) << 6;
        const __half* A = (DUAL && pass) ? A2 : A1;
        const __half* W = (DUAL && pass) ? W2 : W1;
        uint32_t abase = smb + stage * 32768;
        uint32_t bbase = abase + 16384;
#pragma unroll
        for (int t = 0; t < 4; t++) {
            int idx = tid + t * 256;
            int row = idx >> 3, q = idx & 7;
            uint32_t swz = (uint32_t)(q ^ (row & 7)) << 4;
            int gr = bm + row;
            const __half* srcA = A + (size_t)(gr < M ? gr : 0) * K + k0 + q * 8;
            cp_async16(abase + row * 128 + swz, srcA, (gr < M) ? 16 : 0);
            const __half* srcB = W + (size_t)(bn + row) * K + k0 + q * 8;
            cp_async16(bbase + row * 128 + swz, srcB, 16);
        }
    };

    prefetch(0, 0); CP_COMMIT();
    prefetch(1, 1); CP_COMMIT();

    uint32_t a_row_off = (uint32_t)(wm * 64 + (lane & 15)) * 128;
    uint32_t a_gx = (uint32_t)((lane & 7) ^ ((lane >> 4) & 1));
    uint32_t b_row_off = (uint32_t)(wn * 32 + (lane & 7)) * 128;
    uint32_t b_gx = (uint32_t)((lane & 7) ^ ((lane >> 3) & 1));

    int stage = 0;
    for (int it = 0; it < total; it++) {
        CP_WAIT1();
        __syncthreads();
        if (it + 2 < total) {
            int ps = stage + 2; if (ps >= 3) ps -= 3;
            prefetch(it + 2, ps);
        }
        CP_COMMIT();

        uint32_t abase = smb + (uint32_t)stage * 32768;
        uint32_t bbase = abase + 16384;
#pragma unroll
        for (int ks = 0; ks < 4; ks++) {
            uint32_t ag = ((2u * ks) ^ a_gx) << 4;
            uint32_t bg = ((2u * ks) ^ b_gx) << 4;
            uint32_t a[4][4], b[4][2];
#pragma unroll
            for (int mi = 0; mi < 4; mi++)
                ldsm_x4(a[mi], abase + a_row_off + mi * 2048 + ag);
#pragma unroll
            for (int ni = 0; ni < 4; ni++)
                ldsm_x2(b[ni], bbase + b_row_off + ni * 1024 + bg);
#pragma unroll
            for (int mi = 0; mi < 4; mi++)
#pragma unroll
                for (int ni = 0; ni < 4; ni++)
                    mma_f16(acc[mi][ni], a[mi], b[ni]);
        }
        if (++stage == 3) stage = 0;
    }

    int qr = lane >> 2, qc2 = (lane & 3) * 2;
#pragma unroll
    for (int mi = 0; mi < 4; mi++) {
#pragma unroll
        for (int half = 0; half < 2; half++) {
            int row = bm + wm * 64 + mi * 16 + qr + half * 8;
            if (row >= M) continue;
#pragma unroll
            for (int ni = 0; ni < 4; ni++) {
                int col = bn + wn * 32 + ni * 8 + qc2;
                float ox = acc[mi][ni][half * 2 + 0];
                float oy = acc[mi][ni][half * 2 + 1];
                if (SPLIT) {
                    if (col < Nsplit) {
                        *(uint32_t*)((__half*)Cout + (size_t)row * Nsplit + col) = pack_h2(ox, oy);
                    } else {
                        *(float2*)(Cout2 + (size_t)row * (N - Nsplit) + (col - Nsplit)) =
                            make_float2(ox, oy);
                    }
                } else {
                    ox += bias[col]; oy += bias[col + 1];
                    if (RELU) { ox = fmaxf(ox, 0.f); oy = fmaxf(oy, 0.f); }
                    *(uint32_t*)((__half*)Cout + (size_t)row * N + col) = pack_h2(ox, oy);
                }
            }
        }
    }
}

// ===================== launch ==================================================
extern "C" void kernel_launch(void* const* d_in, const int* in_sizes, int n_in,
                              void* d_out, int out_size) {
    const float* x   = (const float*)d_in[0];
    const void*  ei  = d_in[1];
    const float* Wl0 = (const float*)d_in[2];
    const float* bl0 = (const float*)d_in[3];
    const float* Wr0 = (const float*)d_in[4];
    const float* Wl1 = (const float*)d_in[5];
    const float* bl1 = (const float*)d_in[6];
    const float* Wr1 = (const float*)d_in[7];
    const float* Wl2 = (const float*)d_in[8];
    const float* bl2 = (const float*)d_in[9];
    const float* Wr2 = (const float*)d_in[10];
    float*       out = (float*)d_out;

    int M = in_sizes[0] / 128;   // 50000

    __half *aggh, *h1h, *h2h, *xh, *wh, *Pl;
    float* Pr;
    cudaGetSymbolAddress((void**)&aggh, g_aggh);
    cudaGetSymbolAddress((void**)&h1h,  g_h1h);
    cudaGetSymbolAddress((void**)&h2h,  g_h2h);
    cudaGetSymbolAddress((void**)&xh,   g_xh);
    cudaGetSymbolAddress((void**)&wh,   g_wh);
    cudaGetSymbolAddress((void**)&Pl,   g_Pl);
    cudaGetSymbolAddress((void**)&Pr,   g_Pr);

    __half* wl0h = wh;
    __half* wr0h = wh + 65536;
    __half* wl1h = wh + 131072;
    __half* wr1h = wh + 393216;
    __half* wl2h = wh + 655360;   // [Wl2;Wr2] contiguous
    __half* wr2h = wh + 786432;

    cudaFuncSetAttribute(gemm_h_kernel<true, true, false>,
                         cudaFuncAttributeMaxDynamicSharedMemorySize, GEMM_SMEM);
    cudaFuncSetAttribute(gemm_h_kernel<false, false, true>,
                         cudaFuncAttributeMaxDynamicSharedMemorySize, GEMM_SMEM);

    static cudaStream_t s2 = nullptr;
    static cudaEvent_t eFork = nullptr, eJoin = nullptr;
    if (!s2) {
        cudaStreamCreateWithFlags(&s2, cudaStreamNonBlocking);
        cudaEventCreateWithFlags(&eFork, cudaEventDisableTiming);
        cudaEventCreateWithFlags(&eJoin, cudaEventDisableTiming);
    }

    // ---- fork: fp16 conversion on s2, CSR build on the main stream ----
    cudaEventRecord(eFork, 0);
    cudaStreamWaitEvent(s2, eFork, 0);

    RoundArgs ra;
    ra.s[0] = x;   ra.d[0] = xh;   ra.n[0] = M * 128;
    ra.s[1] = Wl0; ra.d[1] = wl0h; ra.n[1] = 512 * 128;
    ra.s[2] = Wr0; ra.d[2] = wr0h; ra.n[2] = 512 * 128;
    ra.s[3] = Wl1; ra.d[3] = wl1h; ra.n[3] = 512 * 512;
    ra.s[4] = Wr1; ra.d[4] = wr1h; ra.n[4] = 512 * 512;
    ra.s[5] = Wl2; ra.d[5] = wl2h; ra.n[5] = 256 * 512;
    ra.s[6] = Wr2; ra.d[6] = wr2h; ra.n[6] = 256 * 512;
    round_all_kernel<<<dim3(256, 7), 256, 0, s2>>>(ra);
    cudaEventRecord(eJoin, s2);

    // CSR build (main stream)
    zero_detect_kernel<<<(N_NODES + 255) / 256, 256>>>((const int*)ei);
    hist_kernel<<<(N_EDGES + 255) / 256, 256>>>(ei);
    scan1_kernel<<<50, 1024>>>();
    scan2_kernel<<<1, 64>>>();
    scan3_kernel<<<50, 1024>>>();
    scatter_kernel<<<(N_EDGES + 255) / 256, 256>>>(ei);

    // ---- join ----
    cudaStreamWaitEvent(0, eJoin, 0);

    int aggBlocks = (N_NODES * 32 + 255) / 256;
    int mTiles = (M + 127) / 128;

    // Layer 0: 128 -> 512, relu (dual GEMM)
    aggregate_kernel<128><<<aggBlocks, 256>>>(xh, aggh);
    gemm_h_kernel<true, true, false><<<dim3(mTiles, 4), 256, GEMM_SMEM>>>(
        aggh, wl0h, xh, wr0h, bl0, h1h, nullptr, M, 512, 128, 0);

    // Layer 1: 512 -> 512, relu (dual GEMM)
    aggregate_kernel<512><<<aggBlocks, 256>>>(h1h, aggh);
    gemm_h_kernel<true, true, false><<<dim3(mTiles, 4), 256, GEMM_SMEM>>>(
        aggh, wl1h, h1h, wr1h, bl1, h2h, nullptr, M, 512, 512, 0);

    // Layer 2 (projection-first, single split GEMM over [Wl2;Wr2])
    gemm_h_kernel<false, false, true><<<dim3(mTiles, 4), 256, GEMM_SMEM>>>(
        h2h, wl2h, nullptr, nullptr, nullptr, Pl, Pr, M, 512, 512, 256);
    final_agg_kernel<<<aggBlocks, 256>>>(Pl, Pr, bl2, out);
}

// round 15
// speedup vs baseline: 1.5029x; 1.0148x over previous
#include <cuda_runtime.h>
#include <cuda_fp16.h>
#include <cstdint>

#define N_NODES 50000
#define N_EDGES 800000

// ===================== scratch =================================================
__device__ __half g_aggh[N_NODES * 512];
__device__ __half g_h1h[N_NODES * 512];
__device__ __half g_h2h[N_NODES * 512];
__device__ __half g_xh[N_NODES * 128];
__device__ __half g_wh[917504];
__device__ __half g_Pl[N_NODES * 256];
__device__ float  g_Pr[N_NODES * 256];
__device__ int    g_deg[N_NODES];
__device__ int    g_off[N_NODES + 1];
__device__ int    g_cur[N_NODES];
__device__ int    g_srcs[N_EDGES];
__device__ int    g_bsum[64];
__device__ int    g_boff[64];
__device__ int    g_idx64;

__device__ __forceinline__ void mma_f16(float* c, const uint32_t* a, const uint32_t* b) {
    asm volatile(
        "mma.sync.aligned.m16n8k16.row.col.f32.f16.f16.f32 "
        "{%0,%1,%2,%3}, {%4,%5,%6,%7}, {%8,%9}, {%0,%1,%2,%3};"
        : "+f"(c[0]), "+f"(c[1]), "+f"(c[2]), "+f"(c[3])
        : "r"(a[0]), "r"(a[1]), "r"(a[2]), "r"(a[3]), "r"(b[0]), "r"(b[1]));
}

__device__ __forceinline__ void ldsm_x4(uint32_t* r, uint32_t addr) {
    asm volatile("ldmatrix.sync.aligned.m8n8.x4.shared.b16 {%0,%1,%2,%3}, [%4];"
                 : "=r"(r[0]), "=r"(r[1]), "=r"(r[2]), "=r"(r[3]) : "r"(addr));
}
__device__ __forceinline__ void ldsm_x2(uint32_t* r, uint32_t addr) {
    asm volatile("ldmatrix.sync.aligned.m8n8.x2.shared.b16 {%0,%1}, [%2];"
                 : "=r"(r[0]), "=r"(r[1]) : "r"(addr));
}

__device__ __forceinline__ void cp_async16(uint32_t dst, const void* src, int sz) {
    asm volatile("cp.async.cg.shared.global [%0], [%1], 16, %2;"
                 :: "r"(dst), "l"(src), "r"(sz) : "memory");
}
#define CP_COMMIT() asm volatile("cp.async.commit_group;" ::: "memory")
#define CP_WAIT1()  asm volatile("cp.async.wait_group 1;" ::: "memory")

__device__ __forceinline__ uint32_t smem_u32(const void* p) {
    uint32_t a;
    asm("{ .reg .u64 t; cvta.to.shared.u64 t, %1; cvt.u32.u64 %0, t; }" : "=r"(a) : "l"(p));
    return a;
}

__device__ __forceinline__ void acc_u32h2(float2& a, uint32_t u) {
    __half2 h = *reinterpret_cast<__half2*>(&u);
    float2 f = __half22float2(h);
    a.x += f.x; a.y += f.y;
}
__device__ __forceinline__ uint32_t pack_h2(float x, float y) {
    __half2 h = __floats2half2_rn(x, y);
    return *reinterpret_cast<uint32_t*>(&h);
}

// ===================== fp32 -> fp16 conversion (x + weights) =================
struct RoundArgs { const float* s[7]; __half* d[7]; int n[7]; };
__global__ void round_all_kernel(RoundArgs ra) {
    int t = blockIdx.y;
    int n4 = ra.n[t] >> 2;
    const float4* s = (const float4*)ra.s[t];
    uint2* d = (uint2*)ra.d[t];
    for (int i = blockIdx.x * blockDim.x + threadIdx.x; i < n4; i += gridDim.x * blockDim.x) {
        float4 v = s[i];
        d[i] = make_uint2(pack_h2(v.x, v.y), pack_h2(v.z, v.w));
    }
}

// ===================== CSR build ==============================================
__global__ void zero_detect_kernel(const int* __restrict__ ei32) {
    int i = blockIdx.x * blockDim.x + threadIdx.x;
    if (i < N_NODES) { g_deg[i] = 0; g_cur[i] = 0; }
    if (blockIdx.x == 0 && threadIdx.x < 32) {
        int lane = threadIdx.x;
        int nz = 0;
#pragma unroll
        for (int t = 0; t < 32; t++) nz |= ei32[1 + 2 * (lane + 32 * t)];
        unsigned any = __ballot_sync(0xffffffffu, nz != 0);
        if (lane == 0) g_idx64 = (any == 0u);
    }
}

__device__ __forceinline__ int load_idx(const void* ei, long long pos) {
    if (g_idx64) return (int)((const long long*)ei)[pos];
    return ((const int*)ei)[pos];
}

__global__ void hist_kernel(const void* __restrict__ ei) {
    int e = blockIdx.x * blockDim.x + threadIdx.x;
    if (e < N_EDGES) {
        int d = load_idx(ei, (long long)N_EDGES + e);
        if ((unsigned)d < (unsigned)N_NODES) atomicAdd(&g_deg[d], 1);
    }
}

__global__ void scan1_kernel() {
    __shared__ int wsum[32];
    int tid = threadIdx.x, b = blockIdx.x;
    int idx = b * 1000 + tid;
    int v = (tid < 1000) ? g_deg[idx] : 0;
    int lane = tid & 31, w = tid >> 5;
    int ix = v;
#pragma unroll
    for (int o = 1; o < 32; o <<= 1) {
        int t = __shfl_up_sync(0xffffffffu, ix, o);
        if (lane >= o) ix += t;
    }
    if (lane == 31) wsum[w] = ix;
    __syncthreads();
    if (w == 0) {
        int t = wsum[lane];
#pragma unroll
        for (int o = 1; o < 32; o <<= 1) {
            int u = __shfl_up_sync(0xffffffffu, t, o);
            if (lane >= o) t += u;
        }
        wsum[lane] = t;
    }
    __syncthreads();
    int excl = ((w > 0) ? wsum[w - 1] : 0) + ix - v;
    if (tid < 1000) g_off[idx] = excl;
    if (tid == 1023) g_bsum[b] = wsum[31];
}

__global__ void scan2_kernel() {
    __shared__ int s[64];
    int tid = threadIdx.x;
    int v = (tid < 50) ? g_bsum[tid] : 0;
    s[tid] = v;
    __syncthreads();
#pragma unroll
    for (int o = 1; o < 64; o <<= 1) {
        int t = (tid >= o) ? s[tid - o] : 0;
        __syncthreads();
        s[tid] += t;
        __syncthreads();
    }
    if (tid < 50) g_boff[tid] = s[tid] - v;
    if (tid == 63) g_off[N_NODES] = s[63];
}

__global__ void scan3_kernel() {
    int tid = threadIdx.x, b = blockIdx.x;
    if (tid < 1000) g_off[b * 1000 + tid] += g_boff[b];
}

__global__ void scatter_kernel(const void* __restrict__ ei) {
    int e = blockIdx.x * blockDim.x + threadIdx.x;
    if (e < N_EDGES) {
        int s = load_idx(ei, e);
        int d = load_idx(ei, (long long)N_EDGES + e);
        if ((unsigned)d < (unsigned)N_NODES && (unsigned)s < (unsigned)N_NODES) {
            int pos = atomicAdd(&g_cur[d], 1);
            g_srcs[g_off[d] + pos] = s;
        }
    }
}

// ===================== fp16 mean aggregation ==================================
// D=512: TWO warps per node — each warp owns a 256-half (512B) column slice.
// Same per-column accumulation order as before -> bit-identical results.
__global__ void aggregate512_kernel(const __half* __restrict__ feat,
                                    __half* __restrict__ out) {
    int gw = (blockIdx.x * blockDim.x + threadIdx.x) >> 5;
    int node = gw >> 1;
    if (node >= N_NODES) return;
    int half = gw & 1;
    int lane = threadIdx.x & 31;
    int beg = g_off[node];
    int end = g_off[node + 1];
    int col = half * 32 + lane;   // uint4 index within a 64-uint4 row

    float2 acc[4];
#pragma unroll
    for (int j = 0; j < 4; j++) acc[j] = make_float2(0.f, 0.f);

    int i = beg;
    for (; i + 3 < end; i += 4) {
        uint4 v0 = __ldg((const uint4*)(feat + (size_t)g_srcs[i] * 512) + col);
        uint4 v1 = __ldg((const uint4*)(feat + (size_t)g_srcs[i + 1] * 512) + col);
        uint4 v2 = __ldg((const uint4*)(feat + (size_t)g_srcs[i + 2] * 512) + col);
        uint4 v3 = __ldg((const uint4*)(feat + (size_t)g_srcs[i + 3] * 512) + col);
        acc_u32h2(acc[0], v0.x); acc_u32h2(acc[0], v1.x);
        acc_u32h2(acc[0], v2.x); acc_u32h2(acc[0], v3.x);
        acc_u32h2(acc[1], v0.y); acc_u32h2(acc[1], v1.y);
        acc_u32h2(acc[1], v2.y); acc_u32h2(acc[1], v3.y);
        acc_u32h2(acc[2], v0.z); acc_u32h2(acc[2], v1.z);
        acc_u32h2(acc[2], v2.z); acc_u32h2(acc[2], v3.z);
        acc_u32h2(acc[3], v0.w); acc_u32h2(acc[3], v1.w);
        acc_u32h2(acc[3], v2.w); acc_u32h2(acc[3], v3.w);
    }
    for (; i < end; i++) {
        uint4 v0 = __ldg((const uint4*)(feat + (size_t)g_srcs[i] * 512) + col);
        acc_u32h2(acc[0], v0.x);
        acc_u32h2(acc[1], v0.y);
        acc_u32h2(acc[2], v0.z);
        acc_u32h2(acc[3], v0.w);
    }
    int cnt = end - beg;
    float inv = 1.0f / (float)(cnt > 0 ? cnt : 1);
    uint4 v;
    v.x = pack_h2(acc[0].x * inv, acc[0].y * inv);
    v.y = pack_h2(acc[1].x * inv, acc[1].y * inv);
    v.z = pack_h2(acc[2].x * inv, acc[2].y * inv);
    v.w = pack_h2(acc[3].x * inv, acc[3].y * inv);
    *((uint4*)(out + (size_t)node * 512) + col) = v;
}

// D=128: one warp per node (unchanged from R10)
__global__ void aggregate128_kernel(const __half* __restrict__ feat,
                                    __half* __restrict__ out) {
    int warp = (blockIdx.x * blockDim.x + threadIdx.x) >> 5;
    if (warp >= N_NODES) return;
    int lane = threadIdx.x & 31;
    int beg = g_off[warp];
    int end = g_off[warp + 1];

    float2 acc[2];
    acc[0] = make_float2(0.f, 0.f); acc[1] = make_float2(0.f, 0.f);
    int i = beg;
    for (; i + 3 < end; i += 4) {
        uint2 v0 = __ldg((const uint2*)(feat + (size_t)g_srcs[i] * 128) + lane);
        uint2 v1 = __ldg((const uint2*)(feat + (size_t)g_srcs[i + 1] * 128) + lane);
        uint2 v2 = __ldg((const uint2*)(feat + (size_t)g_srcs[i + 2] * 128) + lane);
        uint2 v3 = __ldg((const uint2*)(feat + (size_t)g_srcs[i + 3] * 128) + lane);
        acc_u32h2(acc[0], v0.x); acc_u32h2(acc[0], v1.x);
        acc_u32h2(acc[0], v2.x); acc_u32h2(acc[0], v3.x);
        acc_u32h2(acc[1], v0.y); acc_u32h2(acc[1], v1.y);
        acc_u32h2(acc[1], v2.y); acc_u32h2(acc[1], v3.y);
    }
    for (; i < end; i++) {
        uint2 v0 = __ldg((const uint2*)(feat + (size_t)g_srcs[i] * 128) + lane);
        acc_u32h2(acc[0], v0.x);
        acc_u32h2(acc[1], v0.y);
    }
    int cnt = end - beg;
    float inv = 1.0f / (float)(cnt > 0 ? cnt : 1);
    uint2 v;
    v.x = pack_h2(acc[0].x * inv, acc[0].y * inv);
    v.y = pack_h2(acc[1].x * inv, acc[1].y * inv);
    *((uint2*)(out + (size_t)warp * 128) + lane) = v;
}

// ===================== layer-2 final: out = mean(Pl[src]) + Pr[row] + b ========
__global__ void final_agg_kernel(const __half* __restrict__ Pl,
                                 const float* __restrict__ Pr,
                                 const float* __restrict__ bias,
                                 float* __restrict__ out) {
    int warp = (blockIdx.x * blockDim.x + threadIdx.x) >> 5;
    if (warp >= N_NODES) return;
    int lane = threadIdx.x & 31;
    int beg = g_off[warp];
    int end = g_off[warp + 1];

    float2 acc[4];
#pragma unroll
    for (int j = 0; j < 4; j++) acc[j] = make_float2(0.f, 0.f);

    int i = beg;
    for (; i + 3 < end; i += 4) {
        uint4 v0 = __ldg((const uint4*)(Pl + (size_t)g_srcs[i] * 256) + lane);
        uint4 v1 = __ldg((const uint4*)(Pl + (size_t)g_srcs[i + 1] * 256) + lane);
        uint4 v2 = __ldg((const uint4*)(Pl + (size_t)g_srcs[i + 2] * 256) + lane);
        uint4 v3 = __ldg((const uint4*)(Pl + (size_t)g_srcs[i + 3] * 256) + lane);
        acc_u32h2(acc[0], v0.x); acc_u32h2(acc[0], v1.x);
        acc_u32h2(acc[0], v2.x); acc_u32h2(acc[0], v3.x);
        acc_u32h2(acc[1], v0.y); acc_u32h2(acc[1], v1.y);
        acc_u32h2(acc[1], v2.y); acc_u32h2(acc[1], v3.y);
        acc_u32h2(acc[2], v0.z); acc_u32h2(acc[2], v1.z);
        acc_u32h2(acc[2], v2.z); acc_u32h2(acc[2], v3.z);
        acc_u32h2(acc[3], v0.w); acc_u32h2(acc[3], v1.w);
        acc_u32h2(acc[3], v2.w); acc_u32h2(acc[3], v3.w);
    }
    for (; i < end; i++) {
        uint4 v0 = __ldg((const uint4*)(Pl + (size_t)g_srcs[i] * 256) + lane);
        acc_u32h2(acc[0], v0.x);
        acc_u32h2(acc[1], v0.y);
        acc_u32h2(acc[2], v0.z);
        acc_u32h2(acc[3], v0.w);
    }
    int cnt = end - beg;
    float inv = 1.0f / (float)(cnt > 0 ? cnt : 1);
    const float4* pr = (const float4*)(Pr + (size_t)warp * 256 + lane * 8);
    const float4* bb = (const float4*)(bias + lane * 8);
    float4* o = (float4*)(out + (size_t)warp * 256 + lane * 8);
    float4 r0 = __ldg(&pr[0]), r1 = __ldg(&pr[1]);
    float4 b0 = bb[0], b1 = bb[1];
    float4 v0, v1;
    v0.x = acc[0].x * inv + r0.x + b0.x;
    v0.y = acc[0].y * inv + r0.y + b0.y;
    v0.z = acc[1].x * inv + r0.z + b0.z;
    v0.w = acc[1].y * inv + r0.w + b0.w;
    v1.x = acc[2].x * inv + r1.x + b1.x;
    v1.y = acc[2].y * inv + r1.y + b1.y;
    v1.z = acc[3].x * inv + r1.z + b1.z;
    v1.w = acc[3].y * inv + r1.w + b1.w;
    o[0] = v0; o[1] = v1;
}

// ===================== fp16 mma GEMM, cp.async 3-stage, ldmatrix ==============
// DUAL:   C = A1@W1^T + A2@W2^T (+bias,+relu), fp16 out.
// SPLIT:  C = A1@W1^T; cols < Nsplit -> fp16 Cout (stride Nsplit),
//                       cols >= Nsplit -> fp32 Cout2 (stride N-Nsplit).
#define GEMM_SMEM 98304

template <bool DUAL, bool RELU, bool SPLIT>
__global__ void __launch_bounds__(256, 2)
gemm_h_kernel(const __half* __restrict__ A1, const __half* __restrict__ W1,
              const __half* __restrict__ A2, const __half* __restrict__ W2,
              const float* __restrict__ bias, void* __restrict__ Cout,
              float* __restrict__ Cout2, int M, int N, int K, int Nsplit) {
    extern __shared__ uint32_t sm[];
    uint32_t smb = smem_u32(sm);

    int tid = threadIdx.x, lane = tid & 31, wid = tid >> 5;
    int bm = blockIdx.x * 128, bn = blockIdx.y * 128;
    int wm = wid & 1, wn = wid >> 1;

    float acc[4][4][4];
#pragma unroll
    for (int mi = 0; mi < 4; mi++)
#pragma unroll
        for (int ni = 0; ni < 4; ni++)
#pragma unroll
            for (int r = 0; r < 4; r++) acc[mi][ni][r] = 0.0f;

    int chunks = K >> 6;                 // BK = 64 halves
    int total = DUAL ? 2 * chunks : chunks;

    auto prefetch = [&](int it, int stage) {
        int pass = DUAL ? (it >= chunks) : 0;
        int k0 = ((DUAL && pass) ? it - chunks : it) << 6;
        const __half* A = (DUAL && pass) ? A2 : A1;
        const __half* W = (DUAL && pass) ? W2 : W1;
        uint32_t abase = smb + stage * 32768;
        uint32_t bbase = abase + 16384;
#pragma unroll
        for (int t = 0; t < 4; t++) {
            int idx = tid + t * 256;
            int row = idx >> 3, q = idx & 7;
            uint32_t swz = (uint32_t)(q ^ (row & 7)) << 4;
            int gr = bm + row;
            const __half* srcA = A + (size_t)(gr < M ? gr : 0) * K + k0 + q * 8;
            cp_async16(abase + row * 128 + swz, srcA, (gr < M) ? 16 : 0);
            const __half* srcB = W + (size_t)(bn + row) * K + k0 + q * 8;
            cp_async16(bbase + row * 128 + swz, srcB, 16);
        }
    };

    prefetch(0, 0); CP_COMMIT();
    prefetch(1, 1); CP_COMMIT();

    uint32_t a_row_off = (uint32_t)(wm * 64 + (lane & 15)) * 128;
    uint32_t a_gx = (uint32_t)((lane & 7) ^ ((lane >> 4) & 1));
    uint32_t b_row_off = (uint32_t)(wn * 32 + (lane & 7)) * 128;
    uint32_t b_gx = (uint32_t)((lane & 7) ^ ((lane >> 3) & 1));

    int stage = 0;
    for (int it = 0; it < total; it++) {
        CP_WAIT1();
        __syncthreads();
        if (it + 2 < total) {
            int ps = stage + 2; if (ps >= 3) ps -= 3;
            prefetch(it + 2, ps);
        }
        CP_COMMIT();

        uint32_t abase = smb + (uint32_t)stage * 32768;
        uint32_t bbase = abase + 16384;
#pragma unroll
        for (int ks = 0; ks < 4; ks++) {
            uint32_t ag = ((2u * ks) ^ a_gx) << 4;
            uint32_t bg = ((2u * ks) ^ b_gx) << 4;
            uint32_t a[4][4], b[4][2];
#pragma unroll
            for (int mi = 0; mi < 4; mi++)
                ldsm_x4(a[mi], abase + a_row_off + mi * 2048 + ag);
#pragma unroll
            for (int ni = 0; ni < 4; ni++)
                ldsm_x2(b[ni], bbase + b_row_off + ni * 1024 + bg);
#pragma unroll
            for (int mi = 0; mi < 4; mi++)
#pragma unroll
                for (int ni = 0; ni < 4; ni++)
                    mma_f16(acc[mi][ni], a[mi], b[ni]);
        }
        if (++stage == 3) stage = 0;
    }

    int qr = lane >> 2, qc2 = (lane & 3) * 2;
#pragma unroll
    for (int mi = 0; mi < 4; mi++) {
#pragma unroll
        for (int half = 0; half < 2; half++) {
            int row = bm + wm * 64 + mi * 16 + qr + half * 8;
            if (row >= M) continue;
#pragma unroll
            for (int ni = 0; ni < 4; ni++) {
                int col = bn + wn * 32 + ni * 8 + qc2;
                float ox = acc[mi][ni][half * 2 + 0];
                float oy = acc[mi][ni][half * 2 + 1];
                if (SPLIT) {
                    if (col < Nsplit) {
                        *(uint32_t*)((__half*)Cout + (size_t)row * Nsplit + col) = pack_h2(ox, oy);
                    } else {
                        *(float2*)(Cout2 + (size_t)row * (N - Nsplit) + (col - Nsplit)) =
                            make_float2(ox, oy);
                    }
                } else {
                    ox += bias[col]; oy += bias[col + 1];
                    if (RELU) { ox = fmaxf(ox, 0.f); oy = fmaxf(oy, 0.f); }
                    *(uint32_t*)((__half*)Cout + (size_t)row * N + col) = pack_h2(ox, oy);
                }
            }
        }
    }
}

// ===================== launch ==================================================
extern "C" void kernel_launch(void* const* d_in, const int* in_sizes, int n_in,
                              void* d_out, int out_size) {
    const float* x   = (const float*)d_in[0];
    const void*  ei  = d_in[1];
    const float* Wl0 = (const float*)d_in[2];
    const float* bl0 = (const float*)d_in[3];
    const float* Wr0 = (const float*)d_in[4];
    const float* Wl1 = (const float*)d_in[5];
    const float* bl1 = (const float*)d_in[6];
    const float* Wr1 = (const float*)d_in[7];
    const float* Wl2 = (const float*)d_in[8];
    const float* bl2 = (const float*)d_in[9];
    const float* Wr2 = (const float*)d_in[10];
    float*       out = (float*)d_out;

    int M = in_sizes[0] / 128;   // 50000

    __half *aggh, *h1h, *h2h, *xh, *wh, *Pl;
    float* Pr;
    cudaGetSymbolAddress((void**)&aggh, g_aggh);
    cudaGetSymbolAddress((void**)&h1h,  g_h1h);
    cudaGetSymbolAddress((void**)&h2h,  g_h2h);
    cudaGetSymbolAddress((void**)&xh,   g_xh);
    cudaGetSymbolAddress((void**)&wh,   g_wh);
    cudaGetSymbolAddress((void**)&Pl,   g_Pl);
    cudaGetSymbolAddress((void**)&Pr,   g_Pr);

    __half* wl0h = wh;
    __half* wr0h = wh + 65536;
    __half* wl1h = wh + 131072;
    __half* wr1h = wh + 393216;
    __half* wl2h = wh + 655360;   // [Wl2;Wr2] contiguous
    __half* wr2h = wh + 786432;

    cudaFuncSetAttribute(gemm_h_kernel<true, true, false>,
                         cudaFuncAttributeMaxDynamicSharedMemorySize, GEMM_SMEM);
    cudaFuncSetAttribute(gemm_h_kernel<false, false, true>,
                         cudaFuncAttributeMaxDynamicSharedMemorySize, GEMM_SMEM);

    static cudaStream_t s2 = nullptr;
    static cudaEvent_t eFork = nullptr, eJoin = nullptr;
    if (!s2) {
        cudaStreamCreateWithFlags(&s2, cudaStreamNonBlocking);
        cudaEventCreateWithFlags(&eFork, cudaEventDisableTiming);
        cudaEventCreateWithFlags(&eJoin, cudaEventDisableTiming);
    }

    // ---- fork: fp16 conversion on s2, CSR build on the main stream ----
    cudaEventRecord(eFork, 0);
    cudaStreamWaitEvent(s2, eFork, 0);

    RoundArgs ra;
    ra.s[0] = x;   ra.d[0] = xh;   ra.n[0] = M * 128;
    ra.s[1] = Wl0; ra.d[1] = wl0h; ra.n[1] = 512 * 128;
    ra.s[2] = Wr0; ra.d[2] = wr0h; ra.n[2] = 512 * 128;
    ra.s[3] = Wl1; ra.d[3] = wl1h; ra.n[3] = 512 * 512;
    ra.s[4] = Wr1; ra.d[4] = wr1h; ra.n[4] = 512 * 512;
    ra.s[5] = Wl2; ra.d[5] = wl2h; ra.n[5] = 256 * 512;
    ra.s[6] = Wr2; ra.d[6] = wr2h; ra.n[6] = 256 * 512;
    round_all_kernel<<<dim3(256, 7), 256, 0, s2>>>(ra);
    cudaEventRecord(eJoin, s2);

    // CSR build (main stream)
    zero_detect_kernel<<<(N_NODES + 255) / 256, 256>>>((const int*)ei);
    hist_kernel<<<(N_EDGES + 255) / 256, 256>>>(ei);
    scan1_kernel<<<50, 1024>>>();
    scan2_kernel<<<1, 64>>>();
    scan3_kernel<<<50, 1024>>>();
    scatter_kernel<<<(N_EDGES + 255) / 256, 256>>>(ei);

    // ---- join ----
    cudaStreamWaitEvent(0, eJoin, 0);

    int aggBlocks  = (N_NODES * 32 + 255) / 256;       // 1 warp/node
    int aggBlocks2 = (N_NODES * 64 + 255) / 256;       // 2 warps/node
    int mTiles = (M + 127) / 128;

    // Layer 0: 128 -> 512, relu (dual GEMM)
    aggregate128_kernel<<<aggBlocks, 256>>>(xh, aggh);
    gemm_h_kernel<true, true, false><<<dim3(mTiles, 4), 256, GEMM_SMEM>>>(
        aggh, wl0h, xh, wr0h, bl0, h1h, nullptr, M, 512, 128, 0);

    // Layer 1: 512 -> 512, relu (dual GEMM); agg512 with 2 warps/node
    aggregate512_kernel<<<aggBlocks2, 256>>>(h1h, aggh);
    gemm_h_kernel<true, true, false><<<dim3(mTiles, 4), 256, GEMM_SMEM>>>(
        aggh, wl1h, h1h, wr1h, bl1, h2h, nullptr, M, 512, 512, 0);

    // Layer 2 (projection-first, single split GEMM over [Wl2;Wr2])
    gemm_h_kernel<false, false, true><<<dim3(mTiles, 4), 256, GEMM_SMEM>>>(
        h2h, wl2h, nullptr, nullptr, nullptr, Pl, Pr, M, 512, 512, 256);
    final_agg_kernel<<<aggBlocks, 256>>>(Pl, Pr, bl2, out);
}